// round 13
// baseline (speedup 1.0000x reference)
#include <cuda_runtime.h>
#include <cuda_bf16.h>

// out_j = (sum_k (Offset_k*4 + mean_k) * s_k * r[j][k] + T_j*300) / 280
// with s = (S, -S, S) * 20,  r = Rx(pi*Rx)·Ry(pi*Ry)·Rz(pi*Rz).
// Folded: A[j][k] = s_k * r[j][k] * S*20/280,  t_j = T_j*300/280.
//
// R12 finding: ITEMS=8 regressed (wave-quantization tail: 3.46 waves with a
// 46%-full last wave of long blocks). ITEMS=4 is the pipeline optimum.
// This round: ITEMS=4 pipeline + params from g_params (two-kernel split).
// Setup node costs only ~0.6us of graph overhead (R6 vs R7 gap), while the
// fused trig cost regs 46->60 (occ 53->43%) + 0.5us preamble. Combining the
// lean R3 body with the R9 pipeline should give 5 blocks/SM.

#define PI_F 3.14159265358979323846f

// Per-batch folded params: 16 floats per batch (9 matrix, 3 bias, 4 pad).
// __device__ global scratch (no cudaMalloc allowed). Supports B up to 4096.
__device__ float g_params[4096 * 16];

__global__ void setup_params_kernel(const float* __restrict__ R,
                                    const float* __restrict__ T,
                                    const float* __restrict__ S,
                                    int B) {
    int b = blockIdx.x * blockDim.x + threadIdx.x;
    if (b >= B) return;

    float sx, cx, sy, cy, sz, cz;
    sincosf(R[b * 3 + 0] * PI_F, &sx, &cx);
    sincosf(R[b * 3 + 1] * PI_F, &sy, &cy);
    sincosf(R[b * 3 + 2] * PI_F, &sz, &cz);

    // r = rx @ ry @ rz  (matching the JAX reference exactly)
    float r00 = cy * cz;
    float r01 = cy * sz;
    float r02 = -sy;
    float r10 = sx * sy * cz - cx * sz;
    float r11 = cx * cz + sx * sy * sz;
    float r12 = sx * cy;
    float r20 = cx * sy * cz + sx * sz;
    float r21 = cx * sy * sz - sx * cz;
    float r22 = cx * cy;

    float sc = S[b] * (20.0f / 280.0f);   // S_SCALE=20 folded with /280
    float* p = g_params + b * 16;
    // Column signs (+,-,+) folded.
    p[0] = r00 * sc;  p[1] = -r01 * sc;  p[2] = r02 * sc;
    p[3] = r10 * sc;  p[4] = -r11 * sc;  p[5] = r12 * sc;
    p[6] = r20 * sc;  p[7] = -r21 * sc;  p[8] = r22 * sc;
    p[9]  = T[b * 3 + 0] * (300.0f / 280.0f);
    p[10] = T[b * 3 + 1] * (300.0f / 280.0f);
    p[11] = T[b * 3 + 2] * (300.0f / 280.0f);
    p[12] = 0.f; p[13] = 0.f; p[14] = 0.f; p[15] = 0.f;
}

#define XFORM_LANE(V0, V1, V2, O0, O1, O2)                                   \
    do {                                                                     \
        O0 = fmaf(V0, A00, fmaf(V1, A01, fmaf(V2, A02, t0)));                \
        O1 = fmaf(V0, A10, fmaf(V1, A11, fmaf(V2, A12, t1)));                \
        O2 = fmaf(V0, A20, fmaf(V1, A21, fmaf(V2, A22, t2)));                \
    } while (0)

#define XFORM_QUAD(O0, O1, O2, M0, M1, M2, E0, E1, E2)                       \
    do {                                                                     \
        {                                                                    \
            float v0 = fmaf(O0.x, 4.f, M0.x);                                \
            float v1 = fmaf(O1.x, 4.f, M1.x);                                \
            float v2 = fmaf(O2.x, 4.f, M2.x);                                \
            XFORM_LANE(v0, v1, v2, E0.x, E1.x, E2.x);                        \
        }                                                                    \
        {                                                                    \
            float v0 = fmaf(O0.y, 4.f, M0.y);                                \
            float v1 = fmaf(O1.y, 4.f, M1.y);                                \
            float v2 = fmaf(O2.y, 4.f, M2.y);                                \
            XFORM_LANE(v0, v1, v2, E0.y, E1.y, E2.y);                        \
        }                                                                    \
        {                                                                    \
            float v0 = fmaf(O0.z, 4.f, M0.z);                                \
            float v1 = fmaf(O1.z, 4.f, M1.z);                                \
            float v2 = fmaf(O2.z, 4.f, M2.z);                                \
            XFORM_LANE(v0, v1, v2, E0.z, E1.z, E2.z);                        \
        }                                                                    \
        {                                                                    \
            float v0 = fmaf(O0.w, 4.f, M0.w);                                \
            float v1 = fmaf(O1.w, 4.f, M1.w);                                \
            float v2 = fmaf(O2.w, 4.f, M2.w);                                \
            XFORM_LANE(v0, v1, v2, E0.w, E1.w, E2.w);                        \
        }                                                                    \
    } while (0)

// ITEMS=4 prefetch-1 pipeline (R9 structure), params from g_params (R3's
// lean register body). Plain LDG/STG, no hints, no barriers.
template <int ITEMS>
__global__ __launch_bounds__(256)
void transform_kernel(const float4* __restrict__ off,
                      const float4* __restrict__ mean,
                      float4* __restrict__ out,
                      int quads,            // pixels/4 per channel
                      int blocks_per_batch) {
    int b  = blockIdx.x / blocks_per_batch;
    int rb = blockIdx.x - b * blocks_per_batch;
    int q0 = rb * (256 * ITEMS) + threadIdx.x;
    int cbase = b * 3 * quads;

    // Item-0 loads first, params load (L1/L2-hot after wave 1) overlaps.
    float4 a0 = off[cbase + q0];
    float4 a1 = off[cbase + quads + q0];
    float4 a2 = off[cbase + 2 * quads + q0];
    float4 b0 = mean[q0];
    float4 b1 = mean[quads + q0];
    float4 b2 = mean[2 * quads + q0];

    const float* __restrict__ p = g_params + b * 16;
    float A00 = p[0], A01 = p[1], A02 = p[2];
    float A10 = p[3], A11 = p[4], A12 = p[5];
    float A20 = p[6], A21 = p[7], A22 = p[8];
    float t0 = p[9], t1 = p[10], t2 = p[11];

    // Pipelined loop: prefetch item it+1 before computing/storing item it.
#pragma unroll
    for (int it = 0; it < ITEMS; ++it) {
        float4 c0, c1, c2, d0, d1, d2;
        if (it + 1 < ITEMS) {
            int qn = q0 + (it + 1) * 256;
            c0 = off[cbase + qn];
            c1 = off[cbase + quads + qn];
            c2 = off[cbase + 2 * quads + qn];
            d0 = mean[qn];
            d1 = mean[quads + qn];
            d2 = mean[2 * quads + qn];
        }

        int q = q0 + it * 256;
        float4 e0, e1, e2;
        XFORM_QUAD(a0, a1, a2, b0, b1, b2, e0, e1, e2);
        out[cbase + q]             = e0;
        out[cbase + quads + q]     = e1;
        out[cbase + 2 * quads + q] = e2;

        if (it + 1 < ITEMS) {
            a0 = c0; a1 = c1; a2 = c2;
            b0 = d0; b1 = d1; b2 = d2;
        }
    }
}

// Scalar grid-stride fallback for shapes not divisible by the vector tile.
__global__ __launch_bounds__(256)
void transform_scalar_kernel(const float* __restrict__ off,
                             const float* __restrict__ mean,
                             float* __restrict__ out,
                             int B, int pixels) {
    long total = (long)B * pixels;
    long stride = (long)gridDim.x * blockDim.x;
    for (long i = blockIdx.x * (long)blockDim.x + threadIdx.x; i < total; i += stride) {
        int b = (int)(i / pixels);
        int n = (int)(i - (long)b * pixels);
        const float* __restrict__ p = g_params + b * 16;
        long cb = (long)b * 3 * pixels;
        float v0 = fmaf(off[cb + n],              4.f, mean[n]);
        float v1 = fmaf(off[cb + pixels + n],     4.f, mean[pixels + n]);
        float v2 = fmaf(off[cb + 2 * pixels + n], 4.f, mean[2 * pixels + n]);
        out[cb + n]              = fmaf(v0, p[0], fmaf(v1, p[1], fmaf(v2, p[2], p[9])));
        out[cb + pixels + n]     = fmaf(v0, p[3], fmaf(v1, p[4], fmaf(v2, p[5], p[10])));
        out[cb + 2 * pixels + n] = fmaf(v0, p[6], fmaf(v1, p[7], fmaf(v2, p[8], p[11])));
    }
}

extern "C" void kernel_launch(void* const* d_in, const int* in_sizes, int n_in,
                              void* d_out, int out_size) {
    const float* Offset = (const float*)d_in[0];   // (B, 3, 256, 256)
    const float* R      = (const float*)d_in[1];   // (B, 3)
    const float* T      = (const float*)d_in[2];   // (B, 1, 3)
    const float* S      = (const float*)d_in[3];   // (B, 1)
    const float* mean   = (const float*)d_in[4];   // (3, 256, 256)
    float* out          = (float*)d_out;

    int B      = in_sizes[1] / 3;
    int pixels = in_sizes[4] / 3;   // 65536

    // Stage 1: per-batch folded 3x3 matrix + bias (parallel across SMs).
    setup_params_kernel<<<(B + 31) / 32, 32>>>(R, T, S, B);

    // Stage 2: streaming transform, ITEMS=4 prefetch pipeline.
    if ((pixels % 4) == 0 && ((pixels / 4) % (256 * 4)) == 0) {
        constexpr int ITEMS = 4;
        int quads = pixels / 4;
        int blocks_per_batch = quads / (256 * ITEMS);   // 16 for 256x256
        transform_kernel<ITEMS><<<B * blocks_per_batch, 256>>>(
            (const float4*)Offset, (const float4*)mean, (float4*)out,
            quads, blocks_per_batch);
    } else if ((pixels % 4) == 0 && ((pixels / 4) % (256 * 2)) == 0) {
        constexpr int ITEMS = 2;
        int quads = pixels / 4;
        int blocks_per_batch = quads / (256 * ITEMS);
        transform_kernel<ITEMS><<<B * blocks_per_batch, 256>>>(
            (const float4*)Offset, (const float4*)mean, (float4*)out,
            quads, blocks_per_batch);
    } else {
        long total = (long)B * pixels;
        int blocks = (int)((total + 255) / 256);
        if (blocks > 65535 * 32) blocks = 65535 * 32;
        transform_scalar_kernel<<<blocks, 256>>>(Offset, mean, out, B, pixels);
    }
}

// round 14
// speedup vs baseline: 1.0308x; 1.0308x over previous
#include <cuda_runtime.h>
#include <cuda_bf16.h>

// out_j = (sum_k (Offset_k*4 + mean_k) * s_k * r[j][k] + T_j*300) / 280
// with s = (S, -S, S) * 20,  r = Rx(pi*Rx)·Ry(pi*Ry)·Rz(pi*Rz).
// Folded: A[j][k] = s_k * r[j][k] * S*20/280,  t_j = T_j*300/280.
//
// R13 finding: split-vs-fused kernel time identical (59.17 vs 59.23us) but the
// setup node costs ~3.2us of total -> fused ITEMS=4 (R9, 66.4us) is the best
// structure. Kernel plateaued at 59.2us / 73% DRAM across variants.
// This round's ONE variable: __stcs on output stores (touch-once, evict-first)
// to keep L2 capacity for Offset read-ahead + resident mean. Loads unchanged.

#define PI_F 3.14159265358979323846f

// Scratch for the scalar fallback path only (no cudaMalloc allowed).
__device__ float g_params[4096 * 16];

#define XFORM_LANE(V0, V1, V2, O0, O1, O2)                                   \
    do {                                                                     \
        O0 = fmaf(V0, A00, fmaf(V1, A01, fmaf(V2, A02, t0)));                \
        O1 = fmaf(V0, A10, fmaf(V1, A11, fmaf(V2, A12, t1)));                \
        O2 = fmaf(V0, A20, fmaf(V1, A21, fmaf(V2, A22, t2)));                \
    } while (0)

#define XFORM_QUAD(O0, O1, O2, M0, M1, M2, E0, E1, E2)                       \
    do {                                                                     \
        {                                                                    \
            float v0 = fmaf(O0.x, 4.f, M0.x);                                \
            float v1 = fmaf(O1.x, 4.f, M1.x);                                \
            float v2 = fmaf(O2.x, 4.f, M2.x);                                \
            XFORM_LANE(v0, v1, v2, E0.x, E1.x, E2.x);                        \
        }                                                                    \
        {                                                                    \
            float v0 = fmaf(O0.y, 4.f, M0.y);                                \
            float v1 = fmaf(O1.y, 4.f, M1.y);                                \
            float v2 = fmaf(O2.y, 4.f, M2.y);                                \
            XFORM_LANE(v0, v1, v2, E0.y, E1.y, E2.y);                        \
        }                                                                    \
        {                                                                    \
            float v0 = fmaf(O0.z, 4.f, M0.z);                                \
            float v1 = fmaf(O1.z, 4.f, M1.z);                                \
            float v2 = fmaf(O2.z, 4.f, M2.z);                                \
            XFORM_LANE(v0, v1, v2, E0.z, E1.z, E2.z);                        \
        }                                                                    \
        {                                                                    \
            float v0 = fmaf(O0.w, 4.f, M0.w);                                \
            float v1 = fmaf(O1.w, 4.f, M1.w);                                \
            float v2 = fmaf(O2.w, 4.f, M2.w);                                \
            XFORM_LANE(v0, v1, v2, E0.w, E1.w, E2.w);                        \
        }                                                                    \
    } while (0)

template <int ITEMS>
__global__ __launch_bounds__(256)
void transform_fused_kernel(const float4* __restrict__ off,
                            const float4* __restrict__ mean,
                            float4* __restrict__ out,
                            const float* __restrict__ R,
                            const float* __restrict__ T,
                            const float* __restrict__ S,
                            int quads,            // pixels/4 per channel
                            int blocks_per_batch) {
    int b  = blockIdx.x / blocks_per_batch;
    int rb = blockIdx.x - b * blocks_per_batch;
    int q0 = rb * (256 * ITEMS) + threadIdx.x;
    int cbase = b * 3 * quads;
    int lane = threadIdx.x & 31;

    // --- Item-0 loads issued FIRST (in flight during the trig below). ---
    float4 a0 = off[cbase + q0];
    float4 a1 = off[cbase + quads + q0];
    float4 a2 = off[cbase + 2 * quads + q0];
    float4 b0 = mean[q0];
    float4 b1 = mean[quads + q0];
    float4 b2 = mean[2 * quads + q0];

    // --- Warp-level param computation: lanes 0-2 each handle one angle. ---
    float ang = (lane < 3) ? R[b * 3 + lane] * PI_F : 0.0f;
    float s_, c_;
    sincosf(ang, &s_, &c_);
    float sx = __shfl_sync(0xFFFFFFFFu, s_, 0);
    float cx = __shfl_sync(0xFFFFFFFFu, c_, 0);
    float sy = __shfl_sync(0xFFFFFFFFu, s_, 1);
    float cy = __shfl_sync(0xFFFFFFFFu, c_, 1);
    float sz = __shfl_sync(0xFFFFFFFFu, s_, 2);
    float cz = __shfl_sync(0xFFFFFFFFu, c_, 2);

    float tv = (lane < 3) ? T[b * 3 + lane] * (300.0f / 280.0f) : 0.0f;
    float t0 = __shfl_sync(0xFFFFFFFFu, tv, 0);
    float t1 = __shfl_sync(0xFFFFFFFFu, tv, 1);
    float t2 = __shfl_sync(0xFFFFFFFFu, tv, 2);

    float Sv = (lane == 0) ? S[b] : 0.0f;
    float sc = __shfl_sync(0xFFFFFFFFu, Sv, 0) * (20.0f / 280.0f);

    // r = rx @ ry @ rz, column signs (+,-,+) folded (matches JAX reference).
    float A00 = (cy * cz) * sc;
    float A01 = -(cy * sz) * sc;
    float A02 = (-sy) * sc;
    float A10 = (sx * sy * cz - cx * sz) * sc;
    float A11 = -(cx * cz + sx * sy * sz) * sc;
    float A12 = (sx * cy) * sc;
    float A20 = (cx * sy * cz + sx * sz) * sc;
    float A21 = -(cx * sy * sz - sx * cz) * sc;
    float A22 = (cx * cy) * sc;

    // --- Pipelined main loop: prefetch item it+1 before computing item it.
    //     Stores are .cs (evict-first): output is touch-once. ---
#pragma unroll
    for (int it = 0; it < ITEMS; ++it) {
        float4 c0, c1, c2, d0, d1, d2;
        if (it + 1 < ITEMS) {
            int qn = q0 + (it + 1) * 256;
            c0 = off[cbase + qn];
            c1 = off[cbase + quads + qn];
            c2 = off[cbase + 2 * quads + qn];
            d0 = mean[qn];
            d1 = mean[quads + qn];
            d2 = mean[2 * quads + qn];
        }

        int q = q0 + it * 256;
        float4 e0, e1, e2;
        XFORM_QUAD(a0, a1, a2, b0, b1, b2, e0, e1, e2);
        __stcs(out + cbase + q, e0);
        __stcs(out + cbase + quads + q, e1);
        __stcs(out + cbase + 2 * quads + q, e2);

        if (it + 1 < ITEMS) {
            a0 = c0; a1 = c1; a2 = c2;
            b0 = d0; b1 = d1; b2 = d2;
        }
    }
}

// ---------- Scalar fallback path (non-divisible shapes) ----------

__global__ void setup_params_kernel(const float* __restrict__ R,
                                    const float* __restrict__ T,
                                    const float* __restrict__ S,
                                    int B) {
    int b = blockIdx.x * blockDim.x + threadIdx.x;
    if (b >= B) return;

    float sx, cx, sy, cy, sz, cz;
    sincosf(R[b * 3 + 0] * PI_F, &sx, &cx);
    sincosf(R[b * 3 + 1] * PI_F, &sy, &cy);
    sincosf(R[b * 3 + 2] * PI_F, &sz, &cz);

    float r00 = cy * cz;
    float r01 = cy * sz;
    float r02 = -sy;
    float r10 = sx * sy * cz - cx * sz;
    float r11 = cx * cz + sx * sy * sz;
    float r12 = sx * cy;
    float r20 = cx * sy * cz + sx * sz;
    float r21 = cx * sy * sz - sx * cz;
    float r22 = cx * cy;

    float sc = S[b] * (20.0f / 280.0f);
    float* p = g_params + b * 16;
    p[0] = r00 * sc;  p[1] = -r01 * sc;  p[2] = r02 * sc;
    p[3] = r10 * sc;  p[4] = -r11 * sc;  p[5] = r12 * sc;
    p[6] = r20 * sc;  p[7] = -r21 * sc;  p[8] = r22 * sc;
    p[9]  = T[b * 3 + 0] * (300.0f / 280.0f);
    p[10] = T[b * 3 + 1] * (300.0f / 280.0f);
    p[11] = T[b * 3 + 2] * (300.0f / 280.0f);
    p[12] = 0.f; p[13] = 0.f; p[14] = 0.f; p[15] = 0.f;
}

__global__ __launch_bounds__(256)
void transform_scalar_kernel(const float* __restrict__ off,
                             const float* __restrict__ mean,
                             float* __restrict__ out,
                             int B, int pixels) {
    long total = (long)B * pixels;
    long stride = (long)gridDim.x * blockDim.x;
    for (long i = blockIdx.x * (long)blockDim.x + threadIdx.x; i < total; i += stride) {
        int b = (int)(i / pixels);
        int n = (int)(i - (long)b * pixels);
        const float* __restrict__ p = g_params + b * 16;
        long cb = (long)b * 3 * pixels;
        float v0 = fmaf(off[cb + n],              4.f, mean[n]);
        float v1 = fmaf(off[cb + pixels + n],     4.f, mean[pixels + n]);
        float v2 = fmaf(off[cb + 2 * pixels + n], 4.f, mean[2 * pixels + n]);
        out[cb + n]              = fmaf(v0, p[0], fmaf(v1, p[1], fmaf(v2, p[2], p[9])));
        out[cb + pixels + n]     = fmaf(v0, p[3], fmaf(v1, p[4], fmaf(v2, p[5], p[10])));
        out[cb + 2 * pixels + n] = fmaf(v0, p[6], fmaf(v1, p[7], fmaf(v2, p[8], p[11])));
    }
}

extern "C" void kernel_launch(void* const* d_in, const int* in_sizes, int n_in,
                              void* d_out, int out_size) {
    const float* Offset = (const float*)d_in[0];   // (B, 3, 256, 256)
    const float* R      = (const float*)d_in[1];   // (B, 3)
    const float* T      = (const float*)d_in[2];   // (B, 1, 3)
    const float* S      = (const float*)d_in[3];   // (B, 1)
    const float* mean   = (const float*)d_in[4];   // (3, 256, 256)
    float* out          = (float*)d_out;

    int B      = in_sizes[1] / 3;
    int pixels = in_sizes[4] / 3;   // 65536

    if ((pixels % 4) == 0 && ((pixels / 4) % (256 * 4)) == 0) {
        constexpr int ITEMS = 4;
        int quads = pixels / 4;
        int blocks_per_batch = quads / (256 * ITEMS);   // 16 for 256x256
        transform_fused_kernel<ITEMS><<<B * blocks_per_batch, 256>>>(
            (const float4*)Offset, (const float4*)mean, (float4*)out,
            R, T, S, quads, blocks_per_batch);
    } else if ((pixels % 4) == 0 && ((pixels / 4) % (256 * 2)) == 0) {
        constexpr int ITEMS = 2;
        int quads = pixels / 4;
        int blocks_per_batch = quads / (256 * ITEMS);
        transform_fused_kernel<ITEMS><<<B * blocks_per_batch, 256>>>(
            (const float4*)Offset, (const float4*)mean, (float4*)out,
            R, T, S, quads, blocks_per_batch);
    } else {
        setup_params_kernel<<<(B + 31) / 32, 32>>>(R, T, S, B);
        long total = (long)B * pixels;
        int blocks = (int)((total + 255) / 256);
        if (blocks > 65535 * 32) blocks = 65535 * 32;
        transform_scalar_kernel<<<blocks, 256>>>(Offset, mean, out, B, pixels);
    }
}

// round 15
// speedup vs baseline: 1.0318x; 1.0009x over previous
#include <cuda_runtime.h>
#include <cuda_bf16.h>

// out_j = (sum_k (Offset_k*4 + mean_k) * s_k * r[j][k] + T_j*300) / 280
// with s = (S, -S, S) * 20,  r = Rx(pi*Rx)·Ry(pi*Ry)·Rz(pi*Rz).
// Folded: A[j][k] = s_k * r[j][k] * S*20/280,  t_j = T_j*300/280.
//
// FINAL (R9 configuration, session best 66.4us):
//   - single fused kernel (no setup node; R13 showed node costs ~3.2us)
//   - warp-level params: lanes 0-2 sincosf + shfl broadcast, no barrier
//   - ITEMS=4 prefetch-1 pipeline (R9 win: MLP 6->12; R12 showed ITEMS=8
//     regresses via wave-quantization tail)
//   - plain LDG/STG (R14 showed __stcs regresses; R4 showed __ldcs/__ldg+
//     barrier regresses)
// Kernel plateau: 59.2us @ 73% DRAM across 4 structural variants; remaining
// total-kernel gap (~7.2us) is fixed harness/graph-replay overhead.

#define PI_F 3.14159265358979323846f

// Scratch for the scalar fallback path only (no cudaMalloc allowed).
__device__ float g_params[4096 * 16];

#define XFORM_LANE(V0, V1, V2, O0, O1, O2)                                   \
    do {                                                                     \
        O0 = fmaf(V0, A00, fmaf(V1, A01, fmaf(V2, A02, t0)));                \
        O1 = fmaf(V0, A10, fmaf(V1, A11, fmaf(V2, A12, t1)));                \
        O2 = fmaf(V0, A20, fmaf(V1, A21, fmaf(V2, A22, t2)));                \
    } while (0)

#define XFORM_QUAD(O0, O1, O2, M0, M1, M2, E0, E1, E2)                       \
    do {                                                                     \
        {                                                                    \
            float v0 = fmaf(O0.x, 4.f, M0.x);                                \
            float v1 = fmaf(O1.x, 4.f, M1.x);                                \
            float v2 = fmaf(O2.x, 4.f, M2.x);                                \
            XFORM_LANE(v0, v1, v2, E0.x, E1.x, E2.x);                        \
        }                                                                    \
        {                                                                    \
            float v0 = fmaf(O0.y, 4.f, M0.y);                                \
            float v1 = fmaf(O1.y, 4.f, M1.y);                                \
            float v2 = fmaf(O2.y, 4.f, M2.y);                                \
            XFORM_LANE(v0, v1, v2, E0.y, E1.y, E2.y);                        \
        }                                                                    \
        {                                                                    \
            float v0 = fmaf(O0.z, 4.f, M0.z);                                \
            float v1 = fmaf(O1.z, 4.f, M1.z);                                \
            float v2 = fmaf(O2.z, 4.f, M2.z);                                \
            XFORM_LANE(v0, v1, v2, E0.z, E1.z, E2.z);                        \
        }                                                                    \
        {                                                                    \
            float v0 = fmaf(O0.w, 4.f, M0.w);                                \
            float v1 = fmaf(O1.w, 4.f, M1.w);                                \
            float v2 = fmaf(O2.w, 4.f, M2.w);                                \
            XFORM_LANE(v0, v1, v2, E0.w, E1.w, E2.w);                        \
        }                                                                    \
    } while (0)

template <int ITEMS>
__global__ __launch_bounds__(256)
void transform_fused_kernel(const float4* __restrict__ off,
                            const float4* __restrict__ mean,
                            float4* __restrict__ out,
                            const float* __restrict__ R,
                            const float* __restrict__ T,
                            const float* __restrict__ S,
                            int quads,            // pixels/4 per channel
                            int blocks_per_batch) {
    int b  = blockIdx.x / blocks_per_batch;
    int rb = blockIdx.x - b * blocks_per_batch;
    int q0 = rb * (256 * ITEMS) + threadIdx.x;
    int cbase = b * 3 * quads;
    int lane = threadIdx.x & 31;

    // --- Item-0 loads issued FIRST (in flight during the trig below). ---
    float4 a0 = off[cbase + q0];
    float4 a1 = off[cbase + quads + q0];
    float4 a2 = off[cbase + 2 * quads + q0];
    float4 b0 = mean[q0];
    float4 b1 = mean[quads + q0];
    float4 b2 = mean[2 * quads + q0];

    // --- Warp-level param computation: lanes 0-2 each handle one angle. ---
    float ang = (lane < 3) ? R[b * 3 + lane] * PI_F : 0.0f;
    float s_, c_;
    sincosf(ang, &s_, &c_);
    float sx = __shfl_sync(0xFFFFFFFFu, s_, 0);
    float cx = __shfl_sync(0xFFFFFFFFu, c_, 0);
    float sy = __shfl_sync(0xFFFFFFFFu, s_, 1);
    float cy = __shfl_sync(0xFFFFFFFFu, c_, 1);
    float sz = __shfl_sync(0xFFFFFFFFu, s_, 2);
    float cz = __shfl_sync(0xFFFFFFFFu, c_, 2);

    float tv = (lane < 3) ? T[b * 3 + lane] * (300.0f / 280.0f) : 0.0f;
    float t0 = __shfl_sync(0xFFFFFFFFu, tv, 0);
    float t1 = __shfl_sync(0xFFFFFFFFu, tv, 1);
    float t2 = __shfl_sync(0xFFFFFFFFu, tv, 2);

    float Sv = (lane == 0) ? S[b] : 0.0f;
    float sc = __shfl_sync(0xFFFFFFFFu, Sv, 0) * (20.0f / 280.0f);

    // r = rx @ ry @ rz, column signs (+,-,+) folded (matches JAX reference).
    float A00 = (cy * cz) * sc;
    float A01 = -(cy * sz) * sc;
    float A02 = (-sy) * sc;
    float A10 = (sx * sy * cz - cx * sz) * sc;
    float A11 = -(cx * cz + sx * sy * sz) * sc;
    float A12 = (sx * cy) * sc;
    float A20 = (cx * sy * cz + sx * sz) * sc;
    float A21 = -(cx * sy * sz - sx * cz) * sc;
    float A22 = (cx * cy) * sc;

    // --- Pipelined main loop: prefetch item it+1 before computing item it. ---
#pragma unroll
    for (int it = 0; it < ITEMS; ++it) {
        float4 c0, c1, c2, d0, d1, d2;
        if (it + 1 < ITEMS) {
            int qn = q0 + (it + 1) * 256;
            c0 = off[cbase + qn];
            c1 = off[cbase + quads + qn];
            c2 = off[cbase + 2 * quads + qn];
            d0 = mean[qn];
            d1 = mean[quads + qn];
            d2 = mean[2 * quads + qn];
        }

        int q = q0 + it * 256;
        float4 e0, e1, e2;
        XFORM_QUAD(a0, a1, a2, b0, b1, b2, e0, e1, e2);
        out[cbase + q]             = e0;
        out[cbase + quads + q]     = e1;
        out[cbase + 2 * quads + q] = e2;

        if (it + 1 < ITEMS) {
            a0 = c0; a1 = c1; a2 = c2;
            b0 = d0; b1 = d1; b2 = d2;
        }
    }
}

// ---------- Scalar fallback path (non-divisible shapes) ----------

__global__ void setup_params_kernel(const float* __restrict__ R,
                                    const float* __restrict__ T,
                                    const float* __restrict__ S,
                                    int B) {
    int b = blockIdx.x * blockDim.x + threadIdx.x;
    if (b >= B) return;

    float sx, cx, sy, cy, sz, cz;
    sincosf(R[b * 3 + 0] * PI_F, &sx, &cx);
    sincosf(R[b * 3 + 1] * PI_F, &sy, &cy);
    sincosf(R[b * 3 + 2] * PI_F, &sz, &cz);

    float r00 = cy * cz;
    float r01 = cy * sz;
    float r02 = -sy;
    float r10 = sx * sy * cz - cx * sz;
    float r11 = cx * cz + sx * sy * sz;
    float r12 = sx * cy;
    float r20 = cx * sy * cz + sx * sz;
    float r21 = cx * sy * sz - sx * cz;
    float r22 = cx * cy;

    float sc = S[b] * (20.0f / 280.0f);
    float* p = g_params + b * 16;
    p[0] = r00 * sc;  p[1] = -r01 * sc;  p[2] = r02 * sc;
    p[3] = r10 * sc;  p[4] = -r11 * sc;  p[5] = r12 * sc;
    p[6] = r20 * sc;  p[7] = -r21 * sc;  p[8] = r22 * sc;
    p[9]  = T[b * 3 + 0] * (300.0f / 280.0f);
    p[10] = T[b * 3 + 1] * (300.0f / 280.0f);
    p[11] = T[b * 3 + 2] * (300.0f / 280.0f);
    p[12] = 0.f; p[13] = 0.f; p[14] = 0.f; p[15] = 0.f;
}

__global__ __launch_bounds__(256)
void transform_scalar_kernel(const float* __restrict__ off,
                             const float* __restrict__ mean,
                             float* __restrict__ out,
                             int B, int pixels) {
    long total = (long)B * pixels;
    long stride = (long)gridDim.x * blockDim.x;
    for (long i = blockIdx.x * (long)blockDim.x + threadIdx.x; i < total; i += stride) {
        int b = (int)(i / pixels);
        int n = (int)(i - (long)b * pixels);
        const float* __restrict__ p = g_params + b * 16;
        long cb = (long)b * 3 * pixels;
        float v0 = fmaf(off[cb + n],              4.f, mean[n]);
        float v1 = fmaf(off[cb + pixels + n],     4.f, mean[pixels + n]);
        float v2 = fmaf(off[cb + 2 * pixels + n], 4.f, mean[2 * pixels + n]);
        out[cb + n]              = fmaf(v0, p[0], fmaf(v1, p[1], fmaf(v2, p[2], p[9])));
        out[cb + pixels + n]     = fmaf(v0, p[3], fmaf(v1, p[4], fmaf(v2, p[5], p[10])));
        out[cb + 2 * pixels + n] = fmaf(v0, p[6], fmaf(v1, p[7], fmaf(v2, p[8], p[11])));
    }
}

extern "C" void kernel_launch(void* const* d_in, const int* in_sizes, int n_in,
                              void* d_out, int out_size) {
    const float* Offset = (const float*)d_in[0];   // (B, 3, 256, 256)
    const float* R      = (const float*)d_in[1];   // (B, 3)
    const float* T      = (const float*)d_in[2];   // (B, 1, 3)
    const float* S      = (const float*)d_in[3];   // (B, 1)
    const float* mean   = (const float*)d_in[4];   // (3, 256, 256)
    float* out          = (float*)d_out;

    int B      = in_sizes[1] / 3;
    int pixels = in_sizes[4] / 3;   // 65536

    if ((pixels % 4) == 0 && ((pixels / 4) % (256 * 4)) == 0) {
        constexpr int ITEMS = 4;
        int quads = pixels / 4;
        int blocks_per_batch = quads / (256 * ITEMS);   // 16 for 256x256
        transform_fused_kernel<ITEMS><<<B * blocks_per_batch, 256>>>(
            (const float4*)Offset, (const float4*)mean, (float4*)out,
            R, T, S, quads, blocks_per_batch);
    } else if ((pixels % 4) == 0 && ((pixels / 4) % (256 * 2)) == 0) {
        constexpr int ITEMS = 2;
        int quads = pixels / 4;
        int blocks_per_batch = quads / (256 * ITEMS);
        transform_fused_kernel<ITEMS><<<B * blocks_per_batch, 256>>>(
            (const float4*)Offset, (const float4*)mean, (float4*)out,
            R, T, S, quads, blocks_per_batch);
    } else {
        setup_params_kernel<<<(B + 31) / 32, 32>>>(R, T, S, B);
        long total = (long)B * pixels;
        int blocks = (int)((total + 255) / 256);
        if (blocks > 65535 * 32) blocks = 65535 * 32;
        transform_scalar_kernel<<<blocks, 256>>>(Offset, mean, out, B, pixels);
    }
}

// round 16
// speedup vs baseline: 1.0337x; 1.0019x over previous
#include <cuda_runtime.h>
#include <cuda_bf16.h>

// out_j = (sum_k (Offset_k*4 + mean_k) * s_k * r[j][k] + T_j*300) / 280
// with s = (S, -S, S) * 20,  r = Rx(pi*Rx)·Ry(pi*Ry)·Rz(pi*Rz).
// Folded: A[j][k] = s_k * r[j][k] * S*20/280,  t_j = T_j*300/280.
//
// FINAL (R9 configuration; session best 66.4us, noise band 66.4-67.6us):
//   - single fused kernel (no setup node; R13 showed node costs ~3.2us)
//   - warp-level params: lanes 0-2 sincosf + shfl broadcast, no barrier
//   - ITEMS=4 prefetch-1 pipeline (R9 win: MLP 6->12; R12 showed ITEMS=8
//     regresses via wave-quantization tail)
//   - plain LDG/STG (R14 showed __stcs regresses; R4 showed __ldcs/__ldg+
//     barrier regresses)
// Kernel plateau: 59.2-60.0us @ 72-74% DRAM across 5 structural variants;
// app-bytes/time matches DRAM counter (no wasted traffic). Remaining
// total-kernel gap (~7.2us) is fixed harness/graph-replay overhead (R7).
// Run-to-run noise of this exact binary: +-0.8us kernel / +-1.1us total.

#define PI_F 3.14159265358979323846f

// Scratch for the scalar fallback path only (no cudaMalloc allowed).
__device__ float g_params[4096 * 16];

#define XFORM_LANE(V0, V1, V2, O0, O1, O2)                                   \
    do {                                                                     \
        O0 = fmaf(V0, A00, fmaf(V1, A01, fmaf(V2, A02, t0)));                \
        O1 = fmaf(V0, A10, fmaf(V1, A11, fmaf(V2, A12, t1)));                \
        O2 = fmaf(V0, A20, fmaf(V1, A21, fmaf(V2, A22, t2)));                \
    } while (0)

#define XFORM_QUAD(O0, O1, O2, M0, M1, M2, E0, E1, E2)                       \
    do {                                                                     \
        {                                                                    \
            float v0 = fmaf(O0.x, 4.f, M0.x);                                \
            float v1 = fmaf(O1.x, 4.f, M1.x);                                \
            float v2 = fmaf(O2.x, 4.f, M2.x);                                \
            XFORM_LANE(v0, v1, v2, E0.x, E1.x, E2.x);                        \
        }                                                                    \
        {                                                                    \
            float v0 = fmaf(O0.y, 4.f, M0.y);                                \
            float v1 = fmaf(O1.y, 4.f, M1.y);                                \
            float v2 = fmaf(O2.y, 4.f, M2.y);                                \
            XFORM_LANE(v0, v1, v2, E0.y, E1.y, E2.y);                        \
        }                                                                    \
        {                                                                    \
            float v0 = fmaf(O0.z, 4.f, M0.z);                                \
            float v1 = fmaf(O1.z, 4.f, M1.z);                                \
            float v2 = fmaf(O2.z, 4.f, M2.z);                                \
            XFORM_LANE(v0, v1, v2, E0.z, E1.z, E2.z);                        \
        }                                                                    \
        {                                                                    \
            float v0 = fmaf(O0.w, 4.f, M0.w);                                \
            float v1 = fmaf(O1.w, 4.f, M1.w);                                \
            float v2 = fmaf(O2.w, 4.f, M2.w);                                \
            XFORM_LANE(v0, v1, v2, E0.w, E1.w, E2.w);                        \
        }                                                                    \
    } while (0)

template <int ITEMS>
__global__ __launch_bounds__(256)
void transform_fused_kernel(const float4* __restrict__ off,
                            const float4* __restrict__ mean,
                            float4* __restrict__ out,
                            const float* __restrict__ R,
                            const float* __restrict__ T,
                            const float* __restrict__ S,
                            int quads,            // pixels/4 per channel
                            int blocks_per_batch) {
    int b  = blockIdx.x / blocks_per_batch;
    int rb = blockIdx.x - b * blocks_per_batch;
    int q0 = rb * (256 * ITEMS) + threadIdx.x;
    int cbase = b * 3 * quads;
    int lane = threadIdx.x & 31;

    // --- Item-0 loads issued FIRST (in flight during the trig below). ---
    float4 a0 = off[cbase + q0];
    float4 a1 = off[cbase + quads + q0];
    float4 a2 = off[cbase + 2 * quads + q0];
    float4 b0 = mean[q0];
    float4 b1 = mean[quads + q0];
    float4 b2 = mean[2 * quads + q0];

    // --- Warp-level param computation: lanes 0-2 each handle one angle. ---
    float ang = (lane < 3) ? R[b * 3 + lane] * PI_F : 0.0f;
    float s_, c_;
    sincosf(ang, &s_, &c_);
    float sx = __shfl_sync(0xFFFFFFFFu, s_, 0);
    float cx = __shfl_sync(0xFFFFFFFFu, c_, 0);
    float sy = __shfl_sync(0xFFFFFFFFu, s_, 1);
    float cy = __shfl_sync(0xFFFFFFFFu, c_, 1);
    float sz = __shfl_sync(0xFFFFFFFFu, s_, 2);
    float cz = __shfl_sync(0xFFFFFFFFu, c_, 2);

    float tv = (lane < 3) ? T[b * 3 + lane] * (300.0f / 280.0f) : 0.0f;
    float t0 = __shfl_sync(0xFFFFFFFFu, tv, 0);
    float t1 = __shfl_sync(0xFFFFFFFFu, tv, 1);
    float t2 = __shfl_sync(0xFFFFFFFFu, tv, 2);

    float Sv = (lane == 0) ? S[b] : 0.0f;
    float sc = __shfl_sync(0xFFFFFFFFu, Sv, 0) * (20.0f / 280.0f);

    // r = rx @ ry @ rz, column signs (+,-,+) folded (matches JAX reference).
    float A00 = (cy * cz) * sc;
    float A01 = -(cy * sz) * sc;
    float A02 = (-sy) * sc;
    float A10 = (sx * sy * cz - cx * sz) * sc;
    float A11 = -(cx * cz + sx * sy * sz) * sc;
    float A12 = (sx * cy) * sc;
    float A20 = (cx * sy * cz + sx * sz) * sc;
    float A21 = -(cx * sy * sz - sx * cz) * sc;
    float A22 = (cx * cy) * sc;

    // --- Pipelined main loop: prefetch item it+1 before computing item it. ---
#pragma unroll
    for (int it = 0; it < ITEMS; ++it) {
        float4 c0, c1, c2, d0, d1, d2;
        if (it + 1 < ITEMS) {
            int qn = q0 + (it + 1) * 256;
            c0 = off[cbase + qn];
            c1 = off[cbase + quads + qn];
            c2 = off[cbase + 2 * quads + qn];
            d0 = mean[qn];
            d1 = mean[quads + qn];
            d2 = mean[2 * quads + qn];
        }

        int q = q0 + it * 256;
        float4 e0, e1, e2;
        XFORM_QUAD(a0, a1, a2, b0, b1, b2, e0, e1, e2);
        out[cbase + q]             = e0;
        out[cbase + quads + q]     = e1;
        out[cbase + 2 * quads + q] = e2;

        if (it + 1 < ITEMS) {
            a0 = c0; a1 = c1; a2 = c2;
            b0 = d0; b1 = d1; b2 = d2;
        }
    }
}

// ---------- Scalar fallback path (non-divisible shapes) ----------

__global__ void setup_params_kernel(const float* __restrict__ R,
                                    const float* __restrict__ T,
                                    const float* __restrict__ S,
                                    int B) {
    int b = blockIdx.x * blockDim.x + threadIdx.x;
    if (b >= B) return;

    float sx, cx, sy, cy, sz, cz;
    sincosf(R[b * 3 + 0] * PI_F, &sx, &cx);
    sincosf(R[b * 3 + 1] * PI_F, &sy, &cy);
    sincosf(R[b * 3 + 2] * PI_F, &sz, &cz);

    float r00 = cy * cz;
    float r01 = cy * sz;
    float r02 = -sy;
    float r10 = sx * sy * cz - cx * sz;
    float r11 = cx * cz + sx * sy * sz;
    float r12 = sx * cy;
    float r20 = cx * sy * cz + sx * sz;
    float r21 = cx * sy * sz - sx * cz;
    float r22 = cx * cy;

    float sc = S[b] * (20.0f / 280.0f);
    float* p = g_params + b * 16;
    p[0] = r00 * sc;  p[1] = -r01 * sc;  p[2] = r02 * sc;
    p[3] = r10 * sc;  p[4] = -r11 * sc;  p[5] = r12 * sc;
    p[6] = r20 * sc;  p[7] = -r21 * sc;  p[8] = r22 * sc;
    p[9]  = T[b * 3 + 0] * (300.0f / 280.0f);
    p[10] = T[b * 3 + 1] * (300.0f / 280.0f);
    p[11] = T[b * 3 + 2] * (300.0f / 280.0f);
    p[12] = 0.f; p[13] = 0.f; p[14] = 0.f; p[15] = 0.f;
}

__global__ __launch_bounds__(256)
void transform_scalar_kernel(const float* __restrict__ off,
                             const float* __restrict__ mean,
                             float* __restrict__ out,
                             int B, int pixels) {
    long total = (long)B * pixels;
    long stride = (long)gridDim.x * blockDim.x;
    for (long i = blockIdx.x * (long)blockDim.x + threadIdx.x; i < total; i += stride) {
        int b = (int)(i / pixels);
        int n = (int)(i - (long)b * pixels);
        const float* __restrict__ p = g_params + b * 16;
        long cb = (long)b * 3 * pixels;
        float v0 = fmaf(off[cb + n],              4.f, mean[n]);
        float v1 = fmaf(off[cb + pixels + n],     4.f, mean[pixels + n]);
        float v2 = fmaf(off[cb + 2 * pixels + n], 4.f, mean[2 * pixels + n]);
        out[cb + n]              = fmaf(v0, p[0], fmaf(v1, p[1], fmaf(v2, p[2], p[9])));
        out[cb + pixels + n]     = fmaf(v0, p[3], fmaf(v1, p[4], fmaf(v2, p[5], p[10])));
        out[cb + 2 * pixels + n] = fmaf(v0, p[6], fmaf(v1, p[7], fmaf(v2, p[8], p[11])));
    }
}

extern "C" void kernel_launch(void* const* d_in, const int* in_sizes, int n_in,
                              void* d_out, int out_size) {
    const float* Offset = (const float*)d_in[0];   // (B, 3, 256, 256)
    const float* R      = (const float*)d_in[1];   // (B, 3)
    const float* T      = (const float*)d_in[2];   // (B, 1, 3)
    const float* S      = (const float*)d_in[3];   // (B, 1)
    const float* mean   = (const float*)d_in[4];   // (3, 256, 256)
    float* out          = (float*)d_out;

    int B      = in_sizes[1] / 3;
    int pixels = in_sizes[4] / 3;   // 65536

    if ((pixels % 4) == 0 && ((pixels / 4) % (256 * 4)) == 0) {
        constexpr int ITEMS = 4;
        int quads = pixels / 4;
        int blocks_per_batch = quads / (256 * ITEMS);   // 16 for 256x256
        transform_fused_kernel<ITEMS><<<B * blocks_per_batch, 256>>>(
            (const float4*)Offset, (const float4*)mean, (float4*)out,
            R, T, S, quads, blocks_per_batch);
    } else if ((pixels % 4) == 0 && ((pixels / 4) % (256 * 2)) == 0) {
        constexpr int ITEMS = 2;
        int quads = pixels / 4;
        int blocks_per_batch = quads / (256 * ITEMS);
        transform_fused_kernel<ITEMS><<<B * blocks_per_batch, 256>>>(
            (const float4*)Offset, (const float4*)mean, (float4*)out,
            R, T, S, quads, blocks_per_batch);
    } else {
        setup_params_kernel<<<(B + 31) / 32, 32>>>(R, T, S, B);
        long total = (long)B * pixels;
        int blocks = (int)((total + 255) / 256);
        if (blocks > 65535 * 32) blocks = 65535 * 32;
        transform_scalar_kernel<<<blocks, 256>>>(Offset, mean, out, B, pixels);
    }
}

// round 17
// speedup vs baseline: 1.0342x; 1.0005x over previous
#include <cuda_runtime.h>
#include <cuda_bf16.h>

// out_j = (sum_k (Offset_k*4 + mean_k) * s_k * r[j][k] + T_j*300) / 280
// with s = (S, -S, S) * 20,  r = Rx(pi*Rx)·Ry(pi*Ry)·Rz(pi*Rz).
// Folded: A[j][k] = s_k * r[j][k] * S*20/280,  t_j = T_j*300/280.
//
// FINAL (R9 configuration; session best 66.4us, noise band 66.4-67.6us over
// four executions of this exact binary):
//   - single fused kernel (no setup node; R13 showed node costs ~3.2us)
//   - warp-level params: lanes 0-2 sincosf + shfl broadcast, no barrier
//   - ITEMS=4 prefetch-1 pipeline (R9 win: MLP 6->12; R12 showed ITEMS=8
//     regresses via wave-quantization tail)
//   - plain LDG/STG (R14 showed __stcs regresses; R4 showed __ldcs/__ldg+
//     barrier regresses)
// Traffic audit: 5913GB/s x 59.9us = 354MB moved = analytic minimum (~336MB)
// -> zero wasted traffic; kernel is at the mixed-R/W DRAM-turnaround ceiling
// for this access pattern. Total-kernel gap (~7.2us) is fixed harness
// overhead (single-node R7 proof). Noise: +-0.8us kernel / +-1.1us total.

#define PI_F 3.14159265358979323846f

// Scratch for the scalar fallback path only (no cudaMalloc allowed).
__device__ float g_params[4096 * 16];

#define XFORM_LANE(V0, V1, V2, O0, O1, O2)                                   \
    do {                                                                     \
        O0 = fmaf(V0, A00, fmaf(V1, A01, fmaf(V2, A02, t0)));                \
        O1 = fmaf(V0, A10, fmaf(V1, A11, fmaf(V2, A12, t1)));                \
        O2 = fmaf(V0, A20, fmaf(V1, A21, fmaf(V2, A22, t2)));                \
    } while (0)

#define XFORM_QUAD(O0, O1, O2, M0, M1, M2, E0, E1, E2)                       \
    do {                                                                     \
        {                                                                    \
            float v0 = fmaf(O0.x, 4.f, M0.x);                                \
            float v1 = fmaf(O1.x, 4.f, M1.x);                                \
            float v2 = fmaf(O2.x, 4.f, M2.x);                                \
            XFORM_LANE(v0, v1, v2, E0.x, E1.x, E2.x);                        \
        }                                                                    \
        {                                                                    \
            float v0 = fmaf(O0.y, 4.f, M0.y);                                \
            float v1 = fmaf(O1.y, 4.f, M1.y);                                \
            float v2 = fmaf(O2.y, 4.f, M2.y);                                \
            XFORM_LANE(v0, v1, v2, E0.y, E1.y, E2.y);                        \
        }                                                                    \
        {                                                                    \
            float v0 = fmaf(O0.z, 4.f, M0.z);                                \
            float v1 = fmaf(O1.z, 4.f, M1.z);                                \
            float v2 = fmaf(O2.z, 4.f, M2.z);                                \
            XFORM_LANE(v0, v1, v2, E0.z, E1.z, E2.z);                        \
        }                                                                    \
        {                                                                    \
            float v0 = fmaf(O0.w, 4.f, M0.w);                                \
            float v1 = fmaf(O1.w, 4.f, M1.w);                                \
            float v2 = fmaf(O2.w, 4.f, M2.w);                                \
            XFORM_LANE(v0, v1, v2, E0.w, E1.w, E2.w);                        \
        }                                                                    \
    } while (0)

template <int ITEMS>
__global__ __launch_bounds__(256)
void transform_fused_kernel(const float4* __restrict__ off,
                            const float4* __restrict__ mean,
                            float4* __restrict__ out,
                            const float* __restrict__ R,
                            const float* __restrict__ T,
                            const float* __restrict__ S,
                            int quads,            // pixels/4 per channel
                            int blocks_per_batch) {
    int b  = blockIdx.x / blocks_per_batch;
    int rb = blockIdx.x - b * blocks_per_batch;
    int q0 = rb * (256 * ITEMS) + threadIdx.x;
    int cbase = b * 3 * quads;
    int lane = threadIdx.x & 31;

    // --- Item-0 loads issued FIRST (in flight during the trig below). ---
    float4 a0 = off[cbase + q0];
    float4 a1 = off[cbase + quads + q0];
    float4 a2 = off[cbase + 2 * quads + q0];
    float4 b0 = mean[q0];
    float4 b1 = mean[quads + q0];
    float4 b2 = mean[2 * quads + q0];

    // --- Warp-level param computation: lanes 0-2 each handle one angle. ---
    float ang = (lane < 3) ? R[b * 3 + lane] * PI_F : 0.0f;
    float s_, c_;
    sincosf(ang, &s_, &c_);
    float sx = __shfl_sync(0xFFFFFFFFu, s_, 0);
    float cx = __shfl_sync(0xFFFFFFFFu, c_, 0);
    float sy = __shfl_sync(0xFFFFFFFFu, s_, 1);
    float cy = __shfl_sync(0xFFFFFFFFu, c_, 1);
    float sz = __shfl_sync(0xFFFFFFFFu, s_, 2);
    float cz = __shfl_sync(0xFFFFFFFFu, c_, 2);

    float tv = (lane < 3) ? T[b * 3 + lane] * (300.0f / 280.0f) : 0.0f;
    float t0 = __shfl_sync(0xFFFFFFFFu, tv, 0);
    float t1 = __shfl_sync(0xFFFFFFFFu, tv, 1);
    float t2 = __shfl_sync(0xFFFFFFFFu, tv, 2);

    float Sv = (lane == 0) ? S[b] : 0.0f;
    float sc = __shfl_sync(0xFFFFFFFFu, Sv, 0) * (20.0f / 280.0f);

    // r = rx @ ry @ rz, column signs (+,-,+) folded (matches JAX reference).
    float A00 = (cy * cz) * sc;
    float A01 = -(cy * sz) * sc;
    float A02 = (-sy) * sc;
    float A10 = (sx * sy * cz - cx * sz) * sc;
    float A11 = -(cx * cz + sx * sy * sz) * sc;
    float A12 = (sx * cy) * sc;
    float A20 = (cx * sy * cz + sx * sz) * sc;
    float A21 = -(cx * sy * sz - sx * cz) * sc;
    float A22 = (cx * cy) * sc;

    // --- Pipelined main loop: prefetch item it+1 before computing item it. ---
#pragma unroll
    for (int it = 0; it < ITEMS; ++it) {
        float4 c0, c1, c2, d0, d1, d2;
        if (it + 1 < ITEMS) {
            int qn = q0 + (it + 1) * 256;
            c0 = off[cbase + qn];
            c1 = off[cbase + quads + qn];
            c2 = off[cbase + 2 * quads + qn];
            d0 = mean[qn];
            d1 = mean[quads + qn];
            d2 = mean[2 * quads + qn];
        }

        int q = q0 + it * 256;
        float4 e0, e1, e2;
        XFORM_QUAD(a0, a1, a2, b0, b1, b2, e0, e1, e2);
        out[cbase + q]             = e0;
        out[cbase + quads + q]     = e1;
        out[cbase + 2 * quads + q] = e2;

        if (it + 1 < ITEMS) {
            a0 = c0; a1 = c1; a2 = c2;
            b0 = d0; b1 = d1; b2 = d2;
        }
    }
}

// ---------- Scalar fallback path (non-divisible shapes) ----------

__global__ void setup_params_kernel(const float* __restrict__ R,
                                    const float* __restrict__ T,
                                    const float* __restrict__ S,
                                    int B) {
    int b = blockIdx.x * blockDim.x + threadIdx.x;
    if (b >= B) return;

    float sx, cx, sy, cy, sz, cz;
    sincosf(R[b * 3 + 0] * PI_F, &sx, &cx);
    sincosf(R[b * 3 + 1] * PI_F, &sy, &cy);
    sincosf(R[b * 3 + 2] * PI_F, &sz, &cz);

    float r00 = cy * cz;
    float r01 = cy * sz;
    float r02 = -sy;
    float r10 = sx * sy * cz - cx * sz;
    float r11 = cx * cz + sx * sy * sz;
    float r12 = sx * cy;
    float r20 = cx * sy * cz + sx * sz;
    float r21 = cx * sy * sz - sx * cz;
    float r22 = cx * cy;

    float sc = S[b] * (20.0f / 280.0f);
    float* p = g_params + b * 16;
    p[0] = r00 * sc;  p[1] = -r01 * sc;  p[2] = r02 * sc;
    p[3] = r10 * sc;  p[4] = -r11 * sc;  p[5] = r12 * sc;
    p[6] = r20 * sc;  p[7] = -r21 * sc;  p[8] = r22 * sc;
    p[9]  = T[b * 3 + 0] * (300.0f / 280.0f);
    p[10] = T[b * 3 + 1] * (300.0f / 280.0f);
    p[11] = T[b * 3 + 2] * (300.0f / 280.0f);
    p[12] = 0.f; p[13] = 0.f; p[14] = 0.f; p[15] = 0.f;
}

__global__ __launch_bounds__(256)
void transform_scalar_kernel(const float* __restrict__ off,
                             const float* __restrict__ mean,
                             float* __restrict__ out,
                             int B, int pixels) {
    long total = (long)B * pixels;
    long stride = (long)gridDim.x * blockDim.x;
    for (long i = blockIdx.x * (long)blockDim.x + threadIdx.x; i < total; i += stride) {
        int b = (int)(i / pixels);
        int n = (int)(i - (long)b * pixels);
        const float* __restrict__ p = g_params + b * 16;
        long cb = (long)b * 3 * pixels;
        float v0 = fmaf(off[cb + n],              4.f, mean[n]);
        float v1 = fmaf(off[cb + pixels + n],     4.f, mean[pixels + n]);
        float v2 = fmaf(off[cb + 2 * pixels + n], 4.f, mean[2 * pixels + n]);
        out[cb + n]              = fmaf(v0, p[0], fmaf(v1, p[1], fmaf(v2, p[2], p[9])));
        out[cb + pixels + n]     = fmaf(v0, p[3], fmaf(v1, p[4], fmaf(v2, p[5], p[10])));
        out[cb + 2 * pixels + n] = fmaf(v0, p[6], fmaf(v1, p[7], fmaf(v2, p[8], p[11])));
    }
}

extern "C" void kernel_launch(void* const* d_in, const int* in_sizes, int n_in,
                              void* d_out, int out_size) {
    const float* Offset = (const float*)d_in[0];   // (B, 3, 256, 256)
    const float* R      = (const float*)d_in[1];   // (B, 3)
    const float* T      = (const float*)d_in[2];   // (B, 1, 3)
    const float* S      = (const float*)d_in[3];   // (B, 1)
    const float* mean   = (const float*)d_in[4];   // (3, 256, 256)
    float* out          = (float*)d_out;

    int B      = in_sizes[1] / 3;
    int pixels = in_sizes[4] / 3;   // 65536

    if ((pixels % 4) == 0 && ((pixels / 4) % (256 * 4)) == 0) {
        constexpr int ITEMS = 4;
        int quads = pixels / 4;
        int blocks_per_batch = quads / (256 * ITEMS);   // 16 for 256x256
        transform_fused_kernel<ITEMS><<<B * blocks_per_batch, 256>>>(
            (const float4*)Offset, (const float4*)mean, (float4*)out,
            R, T, S, quads, blocks_per_batch);
    } else if ((pixels % 4) == 0 && ((pixels / 4) % (256 * 2)) == 0) {
        constexpr int ITEMS = 2;
        int quads = pixels / 4;
        int blocks_per_batch = quads / (256 * ITEMS);
        transform_fused_kernel<ITEMS><<<B * blocks_per_batch, 256>>>(
            (const float4*)Offset, (const float4*)mean, (float4*)out,
            R, T, S, quads, blocks_per_batch);
    } else {
        setup_params_kernel<<<(B + 31) / 32, 32>>>(R, T, S, B);
        long total = (long)B * pixels;
        int blocks = (int)((total + 255) / 256);
        if (blocks > 65535 * 32) blocks = 65535 * 32;
        transform_scalar_kernel<<<blocks, 256>>>(Offset, mean, out, B, pixels);
    }
}